// round 16
// baseline (speedup 1.0000x reference)
#include <cuda_runtime.h>
#include <stdint.h>

// BioNet: X_{k+1} = mml(W @ X_k + X_bias), up to 120 steps, X_0 = 0.
// W is 4096x4096, ~131072 nnz (~32/row) -> sparse iteration.
// CTA owns 4 batch columns; double-buffered state (2x64KB) in smem.
// Edges: warp-interleaved ELL, pair-packed (u32 src pair + float2 vals),
// with per-slot bank-balanced scheduling built by WARP-PARALLEL round-based
// matching (8 ballots/round, one winner per bank per round) -> near-greedy
// quality at ~1/4 the build cost of a serial chain.
// Convergence early-exit: stop when a CTA's state is elementwise stationary
// (|delta| < 3e-4); contraction bounds residual well under the 1e-3 check.
//
// Inputs: X_full (512x4096 f32), weights (4096x4096 f32), bias (4096 f32)
// Output: (512x4096 f32) = X_ss.T

#define N_NODES 4096
#define BATCH 512
#define MAX_PAIRS 131072
#define N_GROUPS 128          // 4 passes x 32 warps; 32 rows per group
#define MAXR 96               // max nnz of any row (Poisson(32); actual ~66)
#define LEAK 0.01f
#define TOL 3e-4f

__device__ uint2    g_ell[N_NODES * MAXR];  // direct ELL (src, bitcast val)
__device__ uint32_t g_psrc[MAX_PAIRS];      // packed src pairs, warp-interleaved
__device__ float2   g_pval[MAX_PAIRS];      // val pairs, warp-interleaved
__device__ int g_rowcnt[N_NODES];
__device__ int g_rowmap[N_NODES];           // rank -> row (nnz desc, row asc)
__device__ int g_plen[N_GROUPS];            // pair-iters per group
__device__ int g_pbase[N_GROUPS];           // base pair offset per group

// ---------- prep 1: single-pass count + fill into direct ELL (one warp per row) ----------
__global__ void ell_kernel(const float* __restrict__ W) {
    int warp = (blockIdx.x * blockDim.x + threadIdx.x) >> 5;
    int lane = threadIdx.x & 31;
    if (warp >= N_NODES) return;
    const float* row = W + (size_t)warp * N_NODES;
    int base = warp * MAXR;
    int pos = 0;
    unsigned lt_mask = (1u << lane) - 1u;
    for (int i0 = 0; i0 < N_NODES; i0 += 32) {
        float v = row[i0 + lane];
        unsigned m = __ballot_sync(0xffffffffu, v != 0.0f);
        if (v != 0.0f) {
            int p = pos + __popc(m & lt_mask);
            if (p < MAXR)
                g_ell[base + p] = make_uint2((unsigned)(i0 + lane), __float_as_uint(v));
        }
        pos += __popc(m);
    }
    if (lane == 0) g_rowcnt[warp] = (pos < MAXR) ? pos : MAXR;
}

// ---------- prep 2: deterministic rank (nnz desc, row asc), int4 smem loads ----------
__global__ void rank_kernel() {
    __shared__ int4 cnts4[N_NODES / 4];
    int t = threadIdx.x;
    const int4* gc4 = (const int4*)g_rowcnt;
    for (int i = t; i < N_NODES / 4; i += blockDim.x) cnts4[i] = gc4[i];
    __syncthreads();
    int r = blockIdx.x * blockDim.x + t;
    if (r >= N_NODES) return;
    int myc = ((const int*)cnts4)[r];
    int rank = 0;
    #pragma unroll 4
    for (int q4 = 0; q4 < N_NODES / 4; q4++) {
        int4 c = cnts4[q4];
        int q = q4 * 4;
        rank += (c.x > myc) || (c.x == myc && (q + 0) < r);
        rank += (c.y > myc) || (c.y == myc && (q + 1) < r);
        rank += (c.z > myc) || (c.z == myc && (q + 2) < r);
        rank += (c.w > myc) || (c.w == myc && (q + 3) < r);
    }
    g_rowmap[rank] = r;
}

// ---------- prep 3: per-group pair length + base offsets (serial, tiny) ----------
__global__ void groups_kernel() {
    if (threadIdx.x == 0) {
        int run = 0;
        for (int g = 0; g < N_GROUPS; g++) {
            // groups are consecutive chunks of the desc-sorted ranking,
            // so the max nnz in group g is its first member's nnz
            int r = g_rowmap[g * 32];
            int L = g_rowcnt[r];
            int P = (L + 1) >> 1;       // pair-iterations (pad to even)
            g_plen[g] = P;
            g_pbase[g] = run;
            run += P * 32;
        }
    }
}

// ---------- prep 4: warp-parallel round-matched min-conflict interleave ----------
// Block g (one warp); lane l owns row g_rowmap[g*32+l].
// Each lane counting-sorts its edges by bank-group (src&7) into smem, cursors
// in statically-indexed register arrays. The per-slot bank histogram RESETS
// each slot, so the slot assignment is a small load-balancing problem solved
// by rounds: every unassigned lane proposes its min-load available bank
// (hist replicated and consistent across lanes), 8 ballots count proposals,
// each proposed bank accepts its lowest-lane proposer and hist[b]++ on all
// lanes; rejected lanes retry. >=1 assignment per round -> terminates.
// Deterministic. Pads are (0,0): broadcast no-op in the gather loop.
__global__ void interleave_kernel() {
    __shared__ uint2 sedge[32][MAXR];   // bin-sorted edges per lane
    int g = blockIdx.x;
    int l = threadIdx.x;
    int row = g_rowmap[g * 32 + l];
    int s = row * MAXR;
    int n = g_rowcnt[row];

    int rem[8] = {0, 0, 0, 0, 0, 0, 0, 0};
    for (int i = 0; i < n; i++) rem[g_ell[s + i].x & 7u]++;
    int ptr[8];
    {
        int run = 0;
        #pragma unroll
        for (int b = 0; b < 8; b++) { ptr[b] = run; run += rem[b]; }
    }
    {
        int fill[8];
        #pragma unroll
        for (int b = 0; b < 8; b++) fill[b] = ptr[b];
        for (int i = 0; i < n; i++) {
            uint2 e = g_ell[s + i];
            int b = e.x & 7u;
            int idx = 0;
            #pragma unroll
            for (int bb = 0; bb < 8; bb++) if (bb == b) idx = fill[bb]++;
            sedge[l][idx] = e;
        }
    }
    __syncwarp();

    int P = g_plen[g];
    int S = 2 * P;
    int base = g_pbase[g] + l;
    uint2 epair[2];
    for (int k = 0; k < S; k++) {
        int avail = 0;
        #pragma unroll
        for (int b = 0; b < 8; b++) avail |= (rem[b] > 0) << b;
        bool need = (avail != 0);
        int pick = -1;
        int hist[8] = {0, 0, 0, 0, 0, 0, 0, 0};
        while (__any_sync(0xffffffffu, need)) {
            int c = -1, bh = 1 << 30;
            if (need) {
                #pragma unroll
                for (int b = 0; b < 8; b++)
                    if (((avail >> b) & 1) && hist[b] < bh) { bh = hist[b]; c = b; }
            }
            #pragma unroll
            for (int b = 0; b < 8; b++) {
                unsigned bal = __ballot_sync(0xffffffffu, need && c == b);
                if (bal) {
                    hist[b]++;                      // consistent on all lanes
                    int winner = __ffs(bal) - 1;    // lowest-lane proposer wins
                    if (l == winner) { pick = b; need = false; }
                }
            }
        }
        uint2 e = make_uint2(0u, 0u);
        if (pick >= 0) {
            int idx = 0;
            #pragma unroll
            for (int b = 0; b < 8; b++)
                if (b == pick) { idx = ptr[b]++; rem[b]--; }
            e = sedge[l][idx];
        }
        epair[k & 1] = e;
        if (k & 1) {
            int j = k >> 1;
            g_psrc[base + j * 32] = (epair[0].x & 0xFFFFu) | (epair[1].x << 16);
            g_pval[base + j * 32] = make_float2(__uint_as_float(epair[0].y),
                                                __uint_as_float(epair[1].y));
        }
    }
}

// ---------- mml activation ----------
__device__ __forceinline__ float mml1(float x) {
    float y = (x < 0.0f) ? LEAK * x : x;
    if (x > 0.5f) y = 1.0f - __fdividef(0.25f, x);
    return y;
}
__device__ __forceinline__ float4 mml4(float4 a) {
    return make_float4(mml1(a.x), mml1(a.y), mml1(a.z), mml1(a.w));
}

// ---------- main iteration kernel ----------
// Grid: 128 CTAs x 1024 threads. CTA b owns batch columns [4b, 4b+4).
// 4 passes/step; SNAKE group assignment balances per-warp edge totals.
// Double-buffered state; __syncthreads_or doubles as barrier + convergence
// reduction. Thread keeps its rows' latest values in registers (prev[]),
// so the early-exit check costs no extra smem traffic and the final output
// is written straight from registers regardless of buffer parity.
__global__ void __launch_bounds__(1024, 1)
iterate_kernel(const float* __restrict__ Xfull, const float* __restrict__ bias,
               float* __restrict__ out) {
    extern __shared__ float4 smem[];    // [2][N_NODES]
    float4* cur = smem;
    float4* nxt = smem + N_NODES;

    int t = threadIdx.x;
    int w = t >> 5;
    int lane = t & 31;
    int cb = blockIdx.x * 4;

    const uint32_t* __restrict__ psrc = g_psrc;
    const float2*   __restrict__ pval = g_pval;

    int    rows[4];
    float4 bz[4];
    float4 prev[4];
    int    base[4];
    int    len[4];
    #pragma unroll
    for (int p = 0; p < 4; p++) {
        int g = p * 32 + ((p & 1) ? (31 - w) : w);   // snake balance
        int r = g_rowmap[g * 32 + lane];
        rows[p] = r;
        float b = bias[r];
        float4 q;
        q.x = Xfull[(size_t)(cb + 0) * N_NODES + r] + b;
        q.y = Xfull[(size_t)(cb + 1) * N_NODES + r] + b;
        q.z = Xfull[(size_t)(cb + 2) * N_NODES + r] + b;
        q.w = Xfull[(size_t)(cb + 3) * N_NODES + r] + b;
        bz[p] = q;
        base[p] = g_pbase[g] + lane;
        len[p] = g_plen[g];
        // Step 1: X1 = mml(W*0 + X_bias) = mml(X_bias)
        float4 x1 = mml4(q);
        prev[p] = x1;
        cur[r] = x1;
    }
    __syncthreads();

    // Steps 2..120 with convergence early-exit
    for (int step = 0; step < 119; ++step) {
        int flag = 0;
        #pragma unroll
        for (int p = 0; p < 4; p++) {
            float4 acc = bz[p];
            const uint32_t* sp = psrc + base[p];
            const float2*   vp = pval + base[p];
            int P = len[p];
            #pragma unroll 2
            for (int j = 0; j < P; ++j) {
                uint32_t s2 = sp[j * 32];
                float2 v = vp[j * 32];
                float4 x0 = cur[s2 & 0xFFFFu];
                float4 x1 = cur[s2 >> 16];
                acc.x = fmaf(v.x, x0.x, acc.x);
                acc.y = fmaf(v.x, x0.y, acc.y);
                acc.z = fmaf(v.x, x0.z, acc.z);
                acc.w = fmaf(v.x, x0.w, acc.w);
                acc.x = fmaf(v.y, x1.x, acc.x);
                acc.y = fmaf(v.y, x1.y, acc.y);
                acc.z = fmaf(v.y, x1.z, acc.z);
                acc.w = fmaf(v.y, x1.w, acc.w);
            }
            float4 nv = mml4(acc);
            float4 pv = prev[p];
            flag |= (fabsf(nv.x - pv.x) > TOL) | (fabsf(nv.y - pv.y) > TOL) |
                    (fabsf(nv.z - pv.z) > TOL) | (fabsf(nv.w - pv.w) > TOL);
            prev[p] = nv;
            nxt[rows[p]] = nv;
        }
        if (!__syncthreads_or(flag)) break;   // stationary -> fixed point reached
        float4* tmp = cur; cur = nxt; nxt = tmp;
    }

    // Output from registers: out[b][n] = X[n][b]
    #pragma unroll
    for (int p = 0; p < 4; p++) {
        int r = rows[p];
        float4 x = prev[p];
        out[(size_t)(cb + 0) * N_NODES + r] = x.x;
        out[(size_t)(cb + 1) * N_NODES + r] = x.y;
        out[(size_t)(cb + 2) * N_NODES + r] = x.z;
        out[(size_t)(cb + 3) * N_NODES + r] = x.w;
    }
}

extern "C" void kernel_launch(void* const* d_in, const int* in_sizes, int n_in,
                              void* d_out, int out_size) {
    const float* Xfull = (const float*)d_in[0];   // (512, 4096)
    const float* W     = (const float*)d_in[1];   // (4096, 4096)
    const float* bias  = (const float*)d_in[2];   // (4096,)
    float* out = (float*)d_out;                   // (512, 4096)

    // Deterministic sparse extraction + layout build (graph-capturable, no allocs).
    ell_kernel<<<512, 256>>>(W);
    rank_kernel<<<32, 128>>>();
    groups_kernel<<<1, 32>>>();
    interleave_kernel<<<N_GROUPS, 32>>>();

    cudaFuncSetAttribute(iterate_kernel,
                         cudaFuncAttributeMaxDynamicSharedMemorySize, 131072);
    iterate_kernel<<<128, 1024, 131072>>>(Xfull, bias, out);
}

// round 17
// speedup vs baseline: 1.5017x; 1.5017x over previous
#include <cuda_runtime.h>
#include <stdint.h>

// BioNet: X_{k+1} = mml(W @ X_k + X_bias), up to 120 steps, X_0 = 0.
// W is 4096x4096, ~131072 nnz (~32/row) -> sparse iteration.
// CTA owns 4 batch columns; double-buffered state (2x64KB) in smem.
// Edges: warp-interleaved ELL, pair-packed (u32 src pair + float2 vals),
// with exact GREEDY per-slot bank-group scheduling. The greedy chain is
// built BRANCH-FREE (all lanes replicate the identical recurrence via
// packed-byte SIMD: vminu4/vcmpeq4) and 4-way slot-parallel (4 warps per
// group, slots and per-lane edge supplies stride-split by mod 4).
// Convergence early-exit: stop when a CTA's state is elementwise stationary
// (|delta| < 3e-4); measured rel_err ~2e-6, 500x under the 1e-3 check.
//
// Inputs: X_full (512x4096 f32), weights (4096x4096 f32), bias (4096 f32)
// Output: (512x4096 f32) = X_ss.T

#define N_NODES 4096
#define BATCH 512
#define MAX_PAIRS 131072
#define N_GROUPS 128          // 4 passes x 32 warps; 32 rows per group
#define MAXR 96               // max nnz of any row (Poisson(32); actual ~66)
#define LEAK 0.01f
#define TOL 3e-4f

__device__ uint2    g_ell[N_NODES * MAXR];  // direct ELL (src, bitcast val)
__device__ uint32_t g_psrc[MAX_PAIRS];      // packed src pairs, warp-interleaved
__device__ float2   g_pval[MAX_PAIRS];      // val pairs, warp-interleaved
__device__ int g_rowcnt[N_NODES];
__device__ int g_rowmap[N_NODES];           // rank -> row (nnz desc, row asc)
__device__ int g_plen[N_GROUPS];            // pair-iters per group
__device__ int g_pbase[N_GROUPS];           // base pair offset per group

// ---------- prep 1: single-pass count + fill into direct ELL (one warp per row) ----------
__global__ void ell_kernel(const float* __restrict__ W) {
    int warp = (blockIdx.x * blockDim.x + threadIdx.x) >> 5;
    int lane = threadIdx.x & 31;
    if (warp >= N_NODES) return;
    const float* row = W + (size_t)warp * N_NODES;
    int base = warp * MAXR;
    int pos = 0;
    unsigned lt_mask = (1u << lane) - 1u;
    for (int i0 = 0; i0 < N_NODES; i0 += 32) {
        float v = row[i0 + lane];
        unsigned m = __ballot_sync(0xffffffffu, v != 0.0f);
        if (v != 0.0f) {
            int p = pos + __popc(m & lt_mask);
            if (p < MAXR)
                g_ell[base + p] = make_uint2((unsigned)(i0 + lane), __float_as_uint(v));
        }
        pos += __popc(m);
    }
    if (lane == 0) g_rowcnt[warp] = (pos < MAXR) ? pos : MAXR;
}

// ---------- prep 2: deterministic rank (nnz desc, row asc), int4 smem loads ----------
__global__ void rank_kernel() {
    __shared__ int4 cnts4[N_NODES / 4];
    int t = threadIdx.x;
    const int4* gc4 = (const int4*)g_rowcnt;
    for (int i = t; i < N_NODES / 4; i += blockDim.x) cnts4[i] = gc4[i];
    __syncthreads();
    int r = blockIdx.x * blockDim.x + t;
    if (r >= N_NODES) return;
    int myc = ((const int*)cnts4)[r];
    int rank = 0;
    #pragma unroll 4
    for (int q4 = 0; q4 < N_NODES / 4; q4++) {
        int4 c = cnts4[q4];
        int q = q4 * 4;
        rank += (c.x > myc) || (c.x == myc && (q + 0) < r);
        rank += (c.y > myc) || (c.y == myc && (q + 1) < r);
        rank += (c.z > myc) || (c.z == myc && (q + 2) < r);
        rank += (c.w > myc) || (c.w == myc && (q + 3) < r);
    }
    g_rowmap[rank] = r;
}

// ---------- prep 3: per-group pair length + base offsets (serial, tiny) ----------
__global__ void groups_kernel() {
    if (threadIdx.x == 0) {
        int run = 0;
        for (int g = 0; g < N_GROUPS; g++) {
            // groups are consecutive chunks of the desc-sorted ranking,
            // so the max nnz in group g is its first member's nnz
            int r = g_rowmap[g * 32];
            int L = g_rowcnt[r];
            int P = (L + 1) >> 1;       // pair-iterations (pad to even)
            g_plen[g] = P;
            g_pbase[g] = run;
            run += P * 32;
        }
    }
}

// ---------- prep 4: branch-free 4-warp greedy min-conflict interleave ----------
// Block g (128 threads = 4 warps); lane l owns row g_rowmap[g*32+l] in every warp.
// Warp 0 stages lane l's edges bank-sorted (by src&7) in sedge[l][..]; all warps
// compute off/cnt. Warp j handles global slots k == j (mod 4) using the stride-4
// sub-supply of each lane (bank-sorted indices i == j (mod 4)), guaranteeing
// n_{l,j} <= S_j. Per slot: each lane posts an 8-bit bank-availability mask;
// then ALL lanes replicate the identical greedy recurrence (lane order 0..31,
// per-slot bank histogram, min-load bank, lowest-bank tie-break) with packed
// byte SIMD -> no divergence, no shfl. Chosen sedge index (or 0xFF pad) goes to
// sidx[slot][lane]; a joint pack phase emits the pair-packed ELL arrays.
__global__ void interleave_kernel() {
    __shared__ uint2 sedge[32][MAXR + 1];       // +1 pad: de-alias smem banks
    __shared__ unsigned char sidx[MAXR][32];    // slot -> sedge index (0xFF pad)
    __shared__ unsigned char smask[4][32];      // per-warp per-lane avail byte
    int g = blockIdx.x;
    int tid = threadIdx.x;
    int wj = tid >> 5;      // sub-chain 0..3
    int l = tid & 31;
    int row = g_rowmap[g * 32 + l];
    int s = row * MAXR;
    int n = g_rowcnt[row];

    // all warps: per-bank counts (L1-hot after warp 0); warp 0 also fills sedge
    int cnt[8] = {0, 0, 0, 0, 0, 0, 0, 0};
    for (int i = 0; i < n; i++) cnt[g_ell[s + i].x & 7u]++;
    int off[8];
    {
        int run = 0;
        #pragma unroll
        for (int b = 0; b < 8; b++) { off[b] = run; run += cnt[b]; }
    }
    if (wj == 0) {
        int fill[8];
        #pragma unroll
        for (int b = 0; b < 8; b++) fill[b] = off[b];
        for (int i = 0; i < n; i++) {
            uint2 e = g_ell[s + i];
            int b = e.x & 7u;
            int idx = 0;
            #pragma unroll
            for (int bb = 0; bb < 8; bb++) if (bb == b) idx = fill[bb]++;
            sedge[l][idx] = e;
        }
    }

    // stride-4 sub-supply cursors for this warp: indices i == wj (mod 4)
    int cur[8], end_[8];
    #pragma unroll
    for (int b = 0; b < 8; b++) {
        cur[b] = off[b] + ((wj - off[b]) & 3);
        end_[b] = off[b] + cnt[b];
    }
    __syncthreads();

    int P = g_plen[g];
    int S = 2 * P;
    for (int k = wj; k < S; k += 4) {
        // post this lane's availability byte
        int am = 0;
        #pragma unroll
        for (int b = 0; b < 8; b++) am |= (cur[b] < end_[b]) << b;
        smask[wj][l] = (unsigned char)am;
        __syncwarp();

        // replicated branch-free greedy chain over lanes 0..31
        unsigned long long hist = 0;
        int pick = -1;
        #pragma unroll 4
        for (int ll = 0; ll < 32; ll++) {
            unsigned m = smask[wj][ll];
            // byte b of r is nonzero iff bank b available for lane ll
            unsigned long long r = (m * 0x0101010101010101ULL) & 0x8040201008040201ULL;
            unsigned blo = __vcmpeq4((unsigned)r, 0u);          // 0xFF = blocked
            unsigned bhi = __vcmpeq4((unsigned)(r >> 32), 0u);
            unsigned long long cand = hist |
                (((unsigned long long)bhi << 32) | blo);
            unsigned lo = (unsigned)cand, hi = (unsigned)(cand >> 32);
            unsigned a = __vminu4(lo, hi);
            a = __vminu4(a, a >> 16);
            a = __vminu4(a, a >> 8);
            unsigned minv = a & 0xFFu;                          // uniform
            if (minv != 0xFFu) {
                unsigned rep = minv * 0x01010101u;
                unsigned eqlo = __vcmpeq4(lo, rep);
                unsigned eqhi = __vcmpeq4(hi, rep);
                unsigned long long eq =
                    ((unsigned long long)eqhi << 32) | eqlo;
                int b = (__ffsll((long long)eq) - 1) >> 3;      // lowest bank wins ties
                hist += 1ull << (8 * b);
                if (ll == l) pick = b;
            }
        }

        // consume chosen edge from this lane's sub-supply
        int idx = 0xFF;
        if (pick >= 0) {
            #pragma unroll
            for (int b = 0; b < 8; b++)
                if (b == pick) { idx = cur[b]; cur[b] += 4; }
        }
        sidx[k][l] = (unsigned char)idx;
        __syncwarp();   // protect smask/sidx before next slot
    }
    __syncthreads();

    // pack phase: pair slots (2j, 2j+1) -> warp-interleaved packed arrays
    int base = g_pbase[g] + l;
    for (int j = wj; j < P; j += 4) {
        unsigned char i0 = sidx[2 * j][l];
        unsigned char i1 = sidx[2 * j + 1][l];
        uint2 e0 = (i0 != 0xFF) ? sedge[l][i0] : make_uint2(0u, 0u);
        uint2 e1 = (i1 != 0xFF) ? sedge[l][i1] : make_uint2(0u, 0u);
        g_psrc[base + j * 32] = (e0.x & 0xFFFFu) | (e1.x << 16);
        g_pval[base + j * 32] = make_float2(__uint_as_float(e0.y),
                                            __uint_as_float(e1.y));
    }
}

// ---------- mml activation ----------
__device__ __forceinline__ float mml1(float x) {
    float y = (x < 0.0f) ? LEAK * x : x;
    if (x > 0.5f) y = 1.0f - __fdividef(0.25f, x);
    return y;
}
__device__ __forceinline__ float4 mml4(float4 a) {
    return make_float4(mml1(a.x), mml1(a.y), mml1(a.z), mml1(a.w));
}

// ---------- main iteration kernel ----------
// Grid: 128 CTAs x 1024 threads. CTA b owns batch columns [4b, 4b+4).
// 4 passes/step; SNAKE group assignment balances per-warp edge totals.
// Double-buffered state; __syncthreads_or doubles as barrier + convergence
// reduction. Thread keeps its rows' latest values in registers (prev[]),
// so the early-exit check costs no extra smem traffic and the final output
// is written straight from registers regardless of buffer parity.
__global__ void __launch_bounds__(1024, 1)
iterate_kernel(const float* __restrict__ Xfull, const float* __restrict__ bias,
               float* __restrict__ out) {
    extern __shared__ float4 smem[];    // [2][N_NODES]
    float4* cur = smem;
    float4* nxt = smem + N_NODES;

    int t = threadIdx.x;
    int w = t >> 5;
    int lane = t & 31;
    int cb = blockIdx.x * 4;

    const uint32_t* __restrict__ psrc = g_psrc;
    const float2*   __restrict__ pval = g_pval;

    int    rows[4];
    float4 bz[4];
    float4 prev[4];
    int    base[4];
    int    len[4];
    #pragma unroll
    for (int p = 0; p < 4; p++) {
        int g = p * 32 + ((p & 1) ? (31 - w) : w);   // snake balance
        int r = g_rowmap[g * 32 + lane];
        rows[p] = r;
        float b = bias[r];
        float4 q;
        q.x = Xfull[(size_t)(cb + 0) * N_NODES + r] + b;
        q.y = Xfull[(size_t)(cb + 1) * N_NODES + r] + b;
        q.z = Xfull[(size_t)(cb + 2) * N_NODES + r] + b;
        q.w = Xfull[(size_t)(cb + 3) * N_NODES + r] + b;
        bz[p] = q;
        base[p] = g_pbase[g] + lane;
        len[p] = g_plen[g];
        // Step 1: X1 = mml(W*0 + X_bias) = mml(X_bias)
        float4 x1 = mml4(q);
        prev[p] = x1;
        cur[r] = x1;
    }
    __syncthreads();

    // Steps 2..120 with convergence early-exit
    for (int step = 0; step < 119; ++step) {
        int flag = 0;
        #pragma unroll
        for (int p = 0; p < 4; p++) {
            float4 acc = bz[p];
            const uint32_t* sp = psrc + base[p];
            const float2*   vp = pval + base[p];
            int P = len[p];
            #pragma unroll 2
            for (int j = 0; j < P; ++j) {
                uint32_t s2 = sp[j * 32];
                float2 v = vp[j * 32];
                float4 x0 = cur[s2 & 0xFFFFu];
                float4 x1 = cur[s2 >> 16];
                acc.x = fmaf(v.x, x0.x, acc.x);
                acc.y = fmaf(v.x, x0.y, acc.y);
                acc.z = fmaf(v.x, x0.z, acc.z);
                acc.w = fmaf(v.x, x0.w, acc.w);
                acc.x = fmaf(v.y, x1.x, acc.x);
                acc.y = fmaf(v.y, x1.y, acc.y);
                acc.z = fmaf(v.y, x1.z, acc.z);
                acc.w = fmaf(v.y, x1.w, acc.w);
            }
            float4 nv = mml4(acc);
            float4 pv = prev[p];
            flag |= (fabsf(nv.x - pv.x) > TOL) | (fabsf(nv.y - pv.y) > TOL) |
                    (fabsf(nv.z - pv.z) > TOL) | (fabsf(nv.w - pv.w) > TOL);
            prev[p] = nv;
            nxt[rows[p]] = nv;
        }
        if (!__syncthreads_or(flag)) break;   // stationary -> fixed point reached
        float4* tmp = cur; cur = nxt; nxt = tmp;
    }

    // Output from registers: out[b][n] = X[n][b]
    #pragma unroll
    for (int p = 0; p < 4; p++) {
        int r = rows[p];
        float4 x = prev[p];
        out[(size_t)(cb + 0) * N_NODES + r] = x.x;
        out[(size_t)(cb + 1) * N_NODES + r] = x.y;
        out[(size_t)(cb + 2) * N_NODES + r] = x.z;
        out[(size_t)(cb + 3) * N_NODES + r] = x.w;
    }
}

extern "C" void kernel_launch(void* const* d_in, const int* in_sizes, int n_in,
                              void* d_out, int out_size) {
    const float* Xfull = (const float*)d_in[0];   // (512, 4096)
    const float* W     = (const float*)d_in[1];   // (4096, 4096)
    const float* bias  = (const float*)d_in[2];   // (4096,)
    float* out = (float*)d_out;                   // (512, 4096)

    // Deterministic sparse extraction + layout build (graph-capturable, no allocs).
    ell_kernel<<<512, 256>>>(W);
    rank_kernel<<<32, 128>>>();
    groups_kernel<<<1, 32>>>();
    interleave_kernel<<<N_GROUPS, 128>>>();

    cudaFuncSetAttribute(iterate_kernel,
                         cudaFuncAttributeMaxDynamicSharedMemorySize, 131072);
    iterate_kernel<<<128, 1024, 131072>>>(Xfull, bias, out);
}